// round 2
// baseline (speedup 1.0000x reference)
#include <cuda_runtime.h>
#include <math.h>

// Problem constants
#define BB 4096
#define NN 64
#define HD 256
#define UD 128
#define ZD 16
#define AD 64
#define SCALEF 0.25f

// smem layout (floats), padded strides chosen odd (mod 32) for conflict-free
// column access in phase D:
//   sh_h  [64][257]   = 16448
//   sh_z  [64][17]    = 1088
//   shWC  [400][32]   = 12800   (cols 0..15 = ug_w, 16..31 = cand_w)
//   sh_q  [64][64]    = 4096    (aliased by sh_gc [64][33] in phase D)
//   sh_kT [64][65]    = 4160    (kT[d][m])
//   sh_v  [64][64]    = 4096
//   sh_at [64][64]    = 4096
//   sh_c  [64][129]   = 8256
// total = 55040 floats = 220160 bytes
#define SMEM_FLOATS 55040

__device__ __forceinline__ float wsum32(float v) {
    #pragma unroll
    for (int m = 16; m > 0; m >>= 1) v += __shfl_xor_sync(0xffffffffu, v, m);
    return v;
}
__device__ __forceinline__ float wmax32(float v) {
    #pragma unroll
    for (int m = 16; m > 0; m >>= 1) v = fmaxf(v, __shfl_xor_sync(0xffffffffu, v, m));
    return v;
}

__global__ __launch_bounds__(512, 1)
void memetic_fused_kernel(
    const float* __restrict__ h, const float* __restrict__ u, const float* __restrict__ z,
    const float* __restrict__ qd_down, const float* __restrict__ qd_up,
    const float* __restrict__ kd_down, const float* __restrict__ kd_up,
    const float* __restrict__ vd_down, const float* __restrict__ vd_up,
    const float* __restrict__ od_down, const float* __restrict__ od_up,
    const float* __restrict__ ug_w, const float* __restrict__ ug_b,
    const float* __restrict__ cand_w, const float* __restrict__ cand_b,
    const float* __restrict__ eta_logit,
    float* __restrict__ out_c, float* __restrict__ out_z,
    float* __restrict__ out_attn, float* __restrict__ out_q,
    float* __restrict__ out_k, float* __restrict__ out_v)
{
    extern __shared__ float sm[];
    float* sh_h  = sm;                      // 64*257
    float* sh_z  = sh_h + 64 * 257;         // 64*17
    float* shWC  = sh_z + 64 * 17;          // 400*32
    float* sh_q  = shWC + 400 * 32;         // 64*64
    float* sh_kT = sh_q + 64 * 64;          // 64*65
    float* sh_v  = sh_kT + 64 * 65;         // 64*64
    float* sh_at = sh_v + 64 * 64;          // 64*64
    float* sh_c  = sh_at + 64 * 64;         // 64*129
    float* sh_gc = sh_q;                    // alias (64*33 <= 64*64), used after phase C

    const int b    = blockIdx.x;
    const int tid  = threadIdx.x;
    const int wid  = tid >> 5;
    const int lane = tid & 31;
    const float NEG_INF = __int_as_float(0xff800000);

    // ---------------- Phase A: stage h, z, gate weights ----------------
    {
        const float4* hb4 = reinterpret_cast<const float4*>(h + (size_t)b * (NN * HD));
        for (int i4 = tid; i4 < NN * HD / 4; i4 += 512) {
            float4 v4 = hb4[i4];
            int row = i4 >> 6;            // 64 float4 per row
            int col = (i4 & 63) << 2;
            float* d = sh_h + row * 257 + col;
            d[0] = v4.x; d[1] = v4.y; d[2] = v4.z; d[3] = v4.w;
        }
        const float* zb = z + (size_t)b * (NN * ZD);
        for (int i = tid; i < NN * ZD; i += 512) {
            sh_z[(i >> 4) * 17 + (i & 15)] = zb[i];
        }
        for (int i = tid; i < 400 * 32; i += 512) {
            int r = i >> 5, j = i & 31;
            shWC[i] = (j < 16) ? __ldg(ug_w + r * 16 + j) : __ldg(cand_w + r * 16 + (j - 16));
        }
    }
    __syncthreads();

    // ---------------- Phase B: q, k, v (warp per token, 4 tokens/warp) ----------------
    {
        const float* ub = u + (size_t)b * (NN * UD);
        const float4* qdd4 = reinterpret_cast<const float4*>(qd_down);
        const float4* kdd4 = reinterpret_cast<const float4*>(kd_down);
        const float4* vdd4 = reinterpret_cast<const float4*>(vd_down);
        for (int c0 = 0; c0 < 4; c0++) {
            const int t = (wid << 2) + c0;
            // q rank coefficients over concat(h,z) (272 dims)
            float q0 = 0.f, q1 = 0.f, q2 = 0.f, q3 = 0.f;
            for (int i = lane; i < HD + ZD; i += 32) {
                float x = (i < HD) ? sh_h[t * 257 + i] : sh_z[t * 17 + (i - HD)];
                float4 wv = __ldg(qdd4 + i);
                q0 += x * wv.x; q1 += x * wv.y; q2 += x * wv.z; q3 += x * wv.w;
            }
            q0 = wsum32(q0); q1 = wsum32(q1); q2 = wsum32(q2); q3 = wsum32(q3);
            // k, v rank coefficients over u (128 dims)
            float k0 = 0.f, k1 = 0.f, k2 = 0.f, k3 = 0.f;
            float v0 = 0.f, v1 = 0.f, v2 = 0.f, v3 = 0.f;
            #pragma unroll
            for (int it = 0; it < 4; it++) {
                int i = lane + it * 32;
                float x = __ldg(ub + t * UD + i);
                float4 kw = __ldg(kdd4 + i);
                float4 vw = __ldg(vdd4 + i);
                k0 += x * kw.x; k1 += x * kw.y; k2 += x * kw.z; k3 += x * kw.w;
                v0 += x * vw.x; v1 += x * vw.y; v2 += x * vw.z; v3 += x * vw.w;
            }
            k0 = wsum32(k0); k1 = wsum32(k1); k2 = wsum32(k2); k3 = wsum32(k3);
            v0 = wsum32(v0); v1 = wsum32(v1); v2 = wsum32(v2); v3 = wsum32(v3);
            // expand to 64 dims, write smem + gmem
            const size_t tok = (size_t)(b * NN + t);
            #pragma unroll
            for (int s = 0; s < 2; s++) {
                int d = lane + (s << 5);
                float qv = SCALEF * (q0 * __ldg(qd_up + d)       + q1 * __ldg(qd_up + 64 + d)
                                   + q2 * __ldg(qd_up + 128 + d) + q3 * __ldg(qd_up + 192 + d));
                float kv = SCALEF * (k0 * __ldg(kd_up + d)       + k1 * __ldg(kd_up + 64 + d)
                                   + k2 * __ldg(kd_up + 128 + d) + k3 * __ldg(kd_up + 192 + d));
                float vv = SCALEF * (v0 * __ldg(vd_up + d)       + v1 * __ldg(vd_up + 64 + d)
                                   + v2 * __ldg(vd_up + 128 + d) + v3 * __ldg(vd_up + 192 + d));
                sh_q[t * 64 + d]  = qv;
                sh_kT[d * 65 + t] = kv;
                sh_v[t * 64 + d]  = vv;
                out_q[tok * 64 + d] = qv;
                out_k[tok * 64 + d] = kv;
                out_v[tok * 64 + d] = vv;
            }
        }
    }
    __syncthreads();

    // ---------------- Phase C: attention (warp per token-pair) ----------------
    {
        const float4* odd4 = reinterpret_cast<const float4*>(od_down);
        for (int p = 0; p < 2; p++) {
            const int n0 = (wid << 2) + (p << 1);
            const int n1 = n0 + 1;
            float s00 = 0.f, s01 = 0.f, s10 = 0.f, s11 = 0.f;
            #pragma unroll 8
            for (int d = 0; d < 64; d++) {
                float q0 = sh_q[n0 * 64 + d];
                float q1 = sh_q[n1 * 64 + d];
                float ka = sh_kT[d * 65 + lane];
                float kb = sh_kT[d * 65 + lane + 32];
                s00 += q0 * ka; s01 += q0 * kb;
                s10 += q1 * ka; s11 += q1 * kb;
            }
            const float rs = 0.125f;  // 1/sqrt(64)
            s00 *= rs; s01 *= rs; s10 *= rs; s11 *= rs;
            if (lane == n0)       s00 = NEG_INF;
            if (lane + 32 == n0)  s01 = NEG_INF;
            if (lane == n1)       s10 = NEG_INF;
            if (lane + 32 == n1)  s11 = NEG_INF;

            float m0 = wmax32(fmaxf(s00, s01));
            float e00 = __expf(s00 - m0), e01 = __expf(s01 - m0);
            float sum0 = wsum32(e00 + e01);
            float i0 = 1.f / sum0;
            float a00 = e00 * i0, a01 = e01 * i0;

            float m1 = wmax32(fmaxf(s10, s11));
            float e10 = __expf(s10 - m1), e11 = __expf(s11 - m1);
            float sum1 = wsum32(e10 + e11);
            float i1 = 1.f / sum1;
            float a10 = e10 * i1, a11 = e11 * i1;

            sh_at[n0 * 64 + lane]      = a00;
            sh_at[n0 * 64 + lane + 32] = a01;
            sh_at[n1 * 64 + lane]      = a10;
            sh_at[n1 * 64 + lane + 32] = a11;
            {
                size_t tk0 = (size_t)(b * NN + n0) * 64;
                size_t tk1 = (size_t)(b * NN + n1) * 64;
                out_attn[tk0 + lane] = a00; out_attn[tk0 + lane + 32] = a01;
                out_attn[tk1 + lane] = a10; out_attn[tk1 + lane + 32] = a11;
            }
            __syncwarp();

            // c_latent = attn @ v
            float c00 = 0.f, c01 = 0.f, c10 = 0.f, c11 = 0.f;
            #pragma unroll 8
            for (int m = 0; m < 64; m++) {
                float a0 = sh_at[n0 * 64 + m];
                float a1 = sh_at[n1 * 64 + m];
                float va = sh_v[m * 64 + lane];
                float vb = sh_v[m * 64 + lane + 32];
                c00 += a0 * va; c01 += a0 * vb;
                c10 += a1 * va; c11 += a1 * vb;
            }
            // rank-4 output projection, per token
            float4 o0 = __ldg(odd4 + lane);
            float4 o1 = __ldg(odd4 + lane + 32);
            #pragma unroll
            for (int tt = 0; tt < 2; tt++) {
                float ca = (tt == 0) ? c00 : c10;
                float cb = (tt == 0) ? c01 : c11;
                int n = (tt == 0) ? n0 : n1;
                float r0 = wsum32(ca * o0.x + cb * o1.x);
                float r1 = wsum32(ca * o0.y + cb * o1.y);
                float r2 = wsum32(ca * o0.z + cb * o1.z);
                float r3 = wsum32(ca * o0.w + cb * o1.w);
                size_t tk = (size_t)(b * NN + n) * 128;
                #pragma unroll
                for (int s = 0; s < 4; s++) {
                    int j = lane + (s << 5);
                    float cv = SCALEF * (r0 * __ldg(od_up + j)       + r1 * __ldg(od_up + 128 + j)
                                       + r2 * __ldg(od_up + 256 + j) + r3 * __ldg(od_up + 384 + j));
                    sh_c[n * 129 + j] = cv;
                    out_c[tk + j] = cv;
                }
            }
        }
    }
    __syncthreads();

    // ---------------- Phase D: gate/cand matmuls (warp per output-pair, lane per token) ----------------
    {
        const int j0 = wid << 1;     // outputs 2*wid, 2*wid+1 of 32 (0..15 gate, 16..31 cand)
        const int j1 = j0 + 1;
        float bias0, bias1;
        if (j0 < 16) { bias0 = __ldg(ug_b + j0);   bias1 = __ldg(ug_b + j1); }
        else         { bias0 = __ldg(cand_b + j0 - 16); bias1 = __ldg(cand_b + j1 - 16); }
        const int tA = lane, tB = lane + 32;
        float a0A = bias0, a1A = bias1, a0B = bias0, a1B = bias1;
        const float2* WC2 = reinterpret_cast<const float2*>(shWC);  // [400][16] float2

        #pragma unroll
        for (int i = 0; i < 16; i++) {      // z rows
            float2 wv = WC2[i * 16 + wid];
            float xA = sh_z[tA * 17 + i];
            float xB = sh_z[tB * 17 + i];
            a0A += xA * wv.x; a1A += xA * wv.y;
            a0B += xB * wv.x; a1B += xB * wv.y;
        }
        #pragma unroll 8
        for (int i = 0; i < 256; i++) {     // h rows
            float2 wv = WC2[(16 + i) * 16 + wid];
            float xA = sh_h[tA * 257 + i];
            float xB = sh_h[tB * 257 + i];
            a0A += xA * wv.x; a1A += xA * wv.y;
            a0B += xB * wv.x; a1B += xB * wv.y;
        }
        #pragma unroll 8
        for (int i = 0; i < 128; i++) {     // c rows
            float2 wv = WC2[(272 + i) * 16 + wid];
            float xA = sh_c[tA * 129 + i];
            float xB = sh_c[tB * 129 + i];
            a0A += xA * wv.x; a1A += xA * wv.y;
            a0B += xB * wv.x; a1B += xB * wv.y;
        }
        sh_gc[tA * 33 + j0] = a0A; sh_gc[tA * 33 + j1] = a1A;
        sh_gc[tB * 33 + j0] = a0B; sh_gc[tB * 33 + j1] = a1B;
    }
    __syncthreads();

    // ---------------- Phase E: gated update + layernorm ----------------
    {
        const float eta = 1.f / (1.f + __expf(-__ldg(eta_logit)));
        const int s = lane >> 4;
        const int j = lane & 15;
        #pragma unroll
        for (int p = 0; p < 2; p++) {
            int t = (wid << 2) + (p << 1) + s;
            float gp = sh_gc[t * 33 + j];
            float cp = sh_gc[t * 33 + 16 + j];
            float eg = eta * (1.f / (1.f + __expf(-gp)));
            float val = (1.f - eg) * sh_z[t * 17 + j] + eg * tanhf(cp);
            float sum = val;
            #pragma unroll
            for (int msk = 8; msk > 0; msk >>= 1)
                sum += __shfl_xor_sync(0xffffffffu, sum, msk, 16);
            float mu = sum * (1.f / 16.f);
            float dv = val - mu;
            float vs = dv * dv;
            #pragma unroll
            for (int msk = 8; msk > 0; msk >>= 1)
                vs += __shfl_xor_sync(0xffffffffu, vs, msk, 16);
            float var = vs * (1.f / 16.f);
            out_z[(size_t)(b * NN + t) * 16 + j] = dv * rsqrtf(var + 1e-5f);
        }
    }
}

extern "C" void kernel_launch(void* const* d_in, const int* in_sizes, int n_in,
                              void* d_out, int out_size) {
    const float* h        = (const float*)d_in[0];
    const float* u        = (const float*)d_in[1];
    const float* z        = (const float*)d_in[2];
    const float* qd_down  = (const float*)d_in[3];
    const float* qd_up    = (const float*)d_in[4];
    const float* kd_down  = (const float*)d_in[5];
    const float* kd_up    = (const float*)d_in[6];
    const float* vd_down  = (const float*)d_in[7];
    const float* vd_up    = (const float*)d_in[8];
    const float* od_down  = (const float*)d_in[9];
    const float* od_up    = (const float*)d_in[10];
    const float* ug_w     = (const float*)d_in[11];
    const float* ug_b     = (const float*)d_in[12];
    const float* cand_w   = (const float*)d_in[13];
    const float* cand_b   = (const float*)d_in[14];
    const float* eta_logit= (const float*)d_in[15];

    float* o = (float*)d_out;
    // output tuple (c, z_next, attn, q, k, v) concatenated flat
    float* out_c    = o;                                  // 4096*64*128
    float* out_z    = o + (size_t)33554432;               // 4096*64*16
    float* out_attn = o + (size_t)37748736;               // 4096*64*64
    float* out_q    = o + (size_t)54525952;               // 4096*64*64
    float* out_k    = o + (size_t)71303168;               // 4096*64*64
    float* out_v    = o + (size_t)88080384;               // 4096*64*64

    const int smem_bytes = SMEM_FLOATS * sizeof(float);   // 220160
    cudaFuncSetAttribute(memetic_fused_kernel,
                         cudaFuncAttributeMaxDynamicSharedMemorySize, smem_bytes);

    memetic_fused_kernel<<<BB, 512, smem_bytes>>>(
        h, u, z, qd_down, qd_up, kd_down, kd_up, vd_down, vd_up,
        od_down, od_up, ug_w, ug_b, cand_w, cand_b, eta_logit,
        out_c, out_z, out_attn, out_q, out_k, out_v);
}

// round 3
// speedup vs baseline: 1.1974x; 1.1974x over previous
#include <cuda_runtime.h>
#include <math.h>

#define BB 4096
#define NN 64
#define HD 256
#define UD 128
#define ZD 16
#define AD 64
#define SCALEF 0.25f

// smem layout (floats):
//  sh_h  [64][257] = 16448   row-major h
//  sh_z  [64][17]  = 1088
//  shWC  [400][32] = 12800   (j 0..15 gate, 16..31 cand)
//  sh_q  [64][68]  = 4352    q row-major          (aliased: phase-D reduction buffer)
//  sh_kT [64][68]  = 4352    k transposed [d][t]  (aliased: c_latent rows after QK)
//  sh_v  [64][68]  = 4352    v row-major
//  sh_at [64][68]  = 4352    scores -> attn       (aliased: gate/cand buffer [64][33])
//  sh_c  [64][129] = 8256    c rows (128-wide)
// total = 56000 floats = 224000 bytes
#define SMEM_FLOATS 56000

__device__ __forceinline__ float wsum32(float v) {
    #pragma unroll
    for (int m = 16; m > 0; m >>= 1) v += __shfl_xor_sync(0xffffffffu, v, m);
    return v;
}
__device__ __forceinline__ float wmax32(float v) {
    #pragma unroll
    for (int m = 16; m > 0; m >>= 1) v = fmaxf(v, __shfl_xor_sync(0xffffffffu, v, m));
    return v;
}

__global__ __launch_bounds__(512, 1)
void memetic_fused_kernel(
    const float* __restrict__ h, const float* __restrict__ u, const float* __restrict__ z,
    const float* __restrict__ qd_down, const float* __restrict__ qd_up,
    const float* __restrict__ kd_down, const float* __restrict__ kd_up,
    const float* __restrict__ vd_down, const float* __restrict__ vd_up,
    const float* __restrict__ od_down, const float* __restrict__ od_up,
    const float* __restrict__ ug_w, const float* __restrict__ ug_b,
    const float* __restrict__ cand_w, const float* __restrict__ cand_b,
    const float* __restrict__ eta_logit,
    float* __restrict__ out_c, float* __restrict__ out_z,
    float* __restrict__ out_attn, float* __restrict__ out_q,
    float* __restrict__ out_k, float* __restrict__ out_v)
{
    extern __shared__ float sm[];
    float* sh_h  = sm;                  // 16448
    float* sh_z  = sh_h + 16448;        // 1088
    float* shWC  = sh_z + 1088;         // 12800
    float* sh_q  = shWC + 12800;        // 4352
    float* sh_kT = sh_q + 4352;         // 4352
    float* sh_v  = sh_kT + 4352;        // 4352
    float* sh_at = sh_v + 4352;         // 4352
    float* sh_c  = sh_at + 4352;        // 8256
    float* sh_clat = sh_kT;             // alias: c_latent rows [64][68] (kT dead after QK)
    float* sh_red  = sh_q;              // alias: phase-D partials (q/kT dead)
    float* sh_gc   = sh_at;             // alias: gate/cand [64][33] (at dead after AV)

    const int b    = blockIdx.x;
    const int tid  = threadIdx.x;
    const int wid  = tid >> 5;
    const int lane = tid & 31;
    const float NEG_INF = __int_as_float(0xff800000);

    // ---------------- Phase A: stage h, z, gate weights ----------------
    {
        const float* hb = h + (size_t)b * (NN * HD);
        #pragma unroll
        for (int c = 0; c < 4; c++) {
            int row = (wid << 2) + c;
            const float* src = hb + row * HD;
            float* dst = sh_h + row * 257;
            #pragma unroll
            for (int k2 = 0; k2 < 8; k2++)
                dst[lane + (k2 << 5)] = src[lane + (k2 << 5)];
        }
        const float* zb = z + (size_t)b * (NN * ZD);
        for (int i = tid; i < NN * ZD; i += 512)
            sh_z[(i >> 4) * 17 + (i & 15)] = zb[i];
        for (int i = tid; i < 400 * 32; i += 512) {
            int r = i >> 5, j = i & 31;
            shWC[i] = (j < 16) ? __ldg(ug_w + r * 16 + j) : __ldg(cand_w + r * 16 + (j - 16));
        }
    }
    __syncthreads();

    // ---------------- Phase B: q, k, v (warp per token, 4 tokens/warp) ----------------
    {
        const float* ub = u + (size_t)b * (NN * UD);
        const float4* qdd4 = reinterpret_cast<const float4*>(qd_down);
        const float4* kdd4 = reinterpret_cast<const float4*>(kd_down);
        const float4* vdd4 = reinterpret_cast<const float4*>(vd_down);
        for (int c0 = 0; c0 < 4; c0++) {
            const int t = (wid << 2) + c0;
            float q0 = 0.f, q1 = 0.f, q2 = 0.f, q3 = 0.f;
            for (int i = lane; i < HD + ZD; i += 32) {
                float x = (i < HD) ? sh_h[t * 257 + i] : sh_z[t * 17 + (i - HD)];
                float4 wv = __ldg(qdd4 + i);
                q0 += x * wv.x; q1 += x * wv.y; q2 += x * wv.z; q3 += x * wv.w;
            }
            q0 = wsum32(q0); q1 = wsum32(q1); q2 = wsum32(q2); q3 = wsum32(q3);
            float k0 = 0.f, k1 = 0.f, k2 = 0.f, k3 = 0.f;
            float v0 = 0.f, v1 = 0.f, v2 = 0.f, v3 = 0.f;
            #pragma unroll
            for (int it = 0; it < 4; it++) {
                int i = lane + it * 32;
                float x = __ldg(ub + t * UD + i);
                float4 kw = __ldg(kdd4 + i);
                float4 vw = __ldg(vdd4 + i);
                k0 += x * kw.x; k1 += x * kw.y; k2 += x * kw.z; k3 += x * kw.w;
                v0 += x * vw.x; v1 += x * vw.y; v2 += x * vw.z; v3 += x * vw.w;
            }
            k0 = wsum32(k0); k1 = wsum32(k1); k2 = wsum32(k2); k3 = wsum32(k3);
            v0 = wsum32(v0); v1 = wsum32(v1); v2 = wsum32(v2); v3 = wsum32(v3);
            const size_t tok = (size_t)(b * NN + t);
            #pragma unroll
            for (int s = 0; s < 2; s++) {
                int d = lane + (s << 5);
                float qv = SCALEF * (q0 * __ldg(qd_up + d)       + q1 * __ldg(qd_up + 64 + d)
                                   + q2 * __ldg(qd_up + 128 + d) + q3 * __ldg(qd_up + 192 + d));
                float kv = SCALEF * (k0 * __ldg(kd_up + d)       + k1 * __ldg(kd_up + 64 + d)
                                   + k2 * __ldg(kd_up + 128 + d) + k3 * __ldg(kd_up + 192 + d));
                float vv = SCALEF * (v0 * __ldg(vd_up + d)       + v1 * __ldg(vd_up + 64 + d)
                                   + v2 * __ldg(vd_up + 128 + d) + v3 * __ldg(vd_up + 192 + d));
                sh_q[t * 68 + d]  = qv;
                sh_kT[d * 68 + t] = kv;
                sh_v[t * 68 + d]  = vv;
                out_q[tok * 64 + d] = qv;
                out_k[tok * 64 + d] = kv;
                out_v[tok * 64 + d] = vv;
            }
        }
    }
    __syncthreads();

    // ---------------- Phase C1: QK scores (register-tiled GEMM) ----------------
    // warp: 8 n-rows (nb=wid>>1) x 32 m-cols (mh=wid&1); thread: 2n x 4m
    {
        const int nb = wid >> 1, mh = wid & 1;
        const int np = lane & 3, mg = lane >> 2;
        const int n0 = nb * 8 + np * 2;
        const int m0 = mh * 32 + mg * 4;
        float s0x = 0.f, s0y = 0.f, s0z = 0.f, s0w = 0.f;
        float s1x = 0.f, s1y = 0.f, s1z = 0.f, s1w = 0.f;
        #pragma unroll 4
        for (int d = 0; d < 64; d++) {
            float q0 = sh_q[n0 * 68 + d];
            float q1 = sh_q[(n0 + 1) * 68 + d];
            float4 kq = *reinterpret_cast<const float4*>(sh_kT + d * 68 + m0);
            s0x += q0 * kq.x; s0y += q0 * kq.y; s0z += q0 * kq.z; s0w += q0 * kq.w;
            s1x += q1 * kq.x; s1y += q1 * kq.y; s1z += q1 * kq.z; s1w += q1 * kq.w;
        }
        const float rs = 0.125f;
        float4 r0 = make_float4(s0x * rs, s0y * rs, s0z * rs, s0w * rs);
        float4 r1 = make_float4(s1x * rs, s1y * rs, s1z * rs, s1w * rs);
        // self-mask
        if (n0     == m0    ) r0.x = NEG_INF;
        if (n0     == m0 + 1) r0.y = NEG_INF;
        if (n0     == m0 + 2) r0.z = NEG_INF;
        if (n0     == m0 + 3) r0.w = NEG_INF;
        if (n0 + 1 == m0    ) r1.x = NEG_INF;
        if (n0 + 1 == m0 + 1) r1.y = NEG_INF;
        if (n0 + 1 == m0 + 2) r1.z = NEG_INF;
        if (n0 + 1 == m0 + 3) r1.w = NEG_INF;
        *reinterpret_cast<float4*>(sh_at + n0 * 68 + m0)       = r0;
        *reinterpret_cast<float4*>(sh_at + (n0 + 1) * 68 + m0) = r1;
    }
    __syncthreads();

    // ---------------- Phase C1b: softmax (warp per 4 rows) ----------------
    {
        #pragma unroll
        for (int rr = 0; rr < 4; rr++) {
            int n = (wid << 2) + rr;
            float s0 = sh_at[n * 68 + lane];
            float s1 = sh_at[n * 68 + lane + 32];
            float mx = wmax32(fmaxf(s0, s1));
            float e0 = __expf(s0 - mx), e1 = __expf(s1 - mx);
            float inv = 1.f / wsum32(e0 + e1);
            float a0 = e0 * inv, a1 = e1 * inv;
            sh_at[n * 68 + lane]      = a0;
            sh_at[n * 68 + lane + 32] = a1;
            size_t tk = (size_t)(b * NN + n) * 64;
            out_attn[tk + lane]      = a0;
            out_attn[tk + lane + 32] = a1;
        }
    }
    __syncthreads();

    // ---------------- Phase C2: c_latent = attn @ v (register-tiled) ----------------
    {
        const int nb = wid >> 1, dh = wid & 1;
        const int np = lane & 3, dg = lane >> 2;
        const int n0 = nb * 8 + np * 2;
        const int d0 = dh * 32 + dg * 4;
        float c0x = 0.f, c0y = 0.f, c0z = 0.f, c0w = 0.f;
        float c1x = 0.f, c1y = 0.f, c1z = 0.f, c1w = 0.f;
        #pragma unroll 4
        for (int m = 0; m < 64; m++) {
            float a0 = sh_at[n0 * 68 + m];
            float a1 = sh_at[(n0 + 1) * 68 + m];
            float4 vq = *reinterpret_cast<const float4*>(sh_v + m * 68 + d0);
            c0x += a0 * vq.x; c0y += a0 * vq.y; c0z += a0 * vq.z; c0w += a0 * vq.w;
            c1x += a1 * vq.x; c1y += a1 * vq.y; c1z += a1 * vq.z; c1w += a1 * vq.w;
        }
        __syncthreads();   // kT reads done (QK long past); safe to overwrite as clat
        *reinterpret_cast<float4*>(sh_clat + n0 * 68 + d0)       = make_float4(c0x, c0y, c0z, c0w);
        *reinterpret_cast<float4*>(sh_clat + (n0 + 1) * 68 + d0) = make_float4(c1x, c1y, c1z, c1w);
    }
    __syncthreads();

    // ---------------- Phase C3: rank-4 output projection (warp per token) ----------------
    {
        const float4* odd4 = reinterpret_cast<const float4*>(od_down);
        float4 o0 = __ldg(odd4 + lane);
        float4 o1 = __ldg(odd4 + lane + 32);
        for (int c0 = 0; c0 < 4; c0++) {
            int t = (wid << 2) + c0;
            float ca = sh_clat[t * 68 + lane];
            float cb = sh_clat[t * 68 + lane + 32];
            float r0 = wsum32(ca * o0.x + cb * o1.x);
            float r1 = wsum32(ca * o0.y + cb * o1.y);
            float r2 = wsum32(ca * o0.z + cb * o1.z);
            float r3 = wsum32(ca * o0.w + cb * o1.w);
            size_t tk = (size_t)(b * NN + t) * 128;
            #pragma unroll
            for (int s = 0; s < 4; s++) {
                int j = lane + (s << 5);
                float cv = SCALEF * (r0 * __ldg(od_up + j)       + r1 * __ldg(od_up + 128 + j)
                                   + r2 * __ldg(od_up + 256 + j) + r3 * __ldg(od_up + 384 + j));
                sh_c[t * 129 + j] = cv;
                out_c[tk + j] = cv;
            }
        }
    }
    __syncthreads();

    // ---------------- Phase D: gate/cand matmuls, register-tiled ----------------
    // 4 warp-tiles (token-half x out-half), 4 warps split k=400; thread tile 4 tok x 4 out
    {
        const int ip   = wid & 3;           // k-range part
        const int tile = wid >> 2;          // 0..3
        const int th   = wid >> 3;          // token half
        const int oh   = (wid >> 2) & 1;    // output half
        const int tg   = lane & 7;
        const int og   = lane >> 3;
        const int t0   = th * 32 + tg * 4;
        const int j0   = oh * 16 + og * 4;
        float acc[4][4];
        #pragma unroll
        for (int c = 0; c < 4; c++) { acc[c][0]=0.f; acc[c][1]=0.f; acc[c][2]=0.f; acc[c][3]=0.f; }

        const int lo = ip * 100, hi = lo + 100;
        // region z: i in [0,16)
        {
            int a = lo < 0 ? 0 : lo; int bnd = hi < 16 ? hi : 16;
            const float* xb = sh_z + t0 * 17;
            #pragma unroll 2
            for (int i = a; i < bnd; i++) {
                float4 wv = *reinterpret_cast<const float4*>(shWC + i * 32 + j0);
                #pragma unroll
                for (int c = 0; c < 4; c++) {
                    float x = xb[c * 17 + i];
                    acc[c][0] += x * wv.x; acc[c][1] += x * wv.y;
                    acc[c][2] += x * wv.z; acc[c][3] += x * wv.w;
                }
            }
        }
        // region h: i in [16,272)
        {
            int a = lo < 16 ? 16 : lo; int bnd = hi < 272 ? hi : 272;
            const float* xb = sh_h + t0 * 257 - 16;
            #pragma unroll 2
            for (int i = a; i < bnd; i++) {
                float4 wv = *reinterpret_cast<const float4*>(shWC + i * 32 + j0);
                #pragma unroll
                for (int c = 0; c < 4; c++) {
                    float x = xb[c * 257 + i];
                    acc[c][0] += x * wv.x; acc[c][1] += x * wv.y;
                    acc[c][2] += x * wv.z; acc[c][3] += x * wv.w;
                }
            }
        }
        // region c: i in [272,400)
        {
            int a = lo < 272 ? 272 : lo; int bnd = hi;
            const float* xb = sh_c + t0 * 129 - 272;
            #pragma unroll 2
            for (int i = a; i < bnd; i++) {
                float4 wv = *reinterpret_cast<const float4*>(shWC + i * 32 + j0);
                #pragma unroll
                for (int c = 0; c < 4; c++) {
                    float x = xb[c * 129 + i];
                    acc[c][0] += x * wv.x; acc[c][1] += x * wv.y;
                    acc[c][2] += x * wv.z; acc[c][3] += x * wv.w;
                }
            }
        }
        __syncthreads();   // sh_q/sh_kT (clat) fully dead -> reuse as reduction buffer
        if (ip != 0) {
            float* dst = sh_red + (tile * 3 + (ip - 1)) * 512;
            #pragma unroll
            for (int c = 0; c < 4; c++)
                #pragma unroll
                for (int d = 0; d < 4; d++)
                    dst[(c * 4 + d) * 32 + lane] = acc[c][d];
        }
        __syncthreads();
        if (ip == 0) {
            #pragma unroll
            for (int s = 0; s < 3; s++) {
                const float* src = sh_red + (tile * 3 + s) * 512;
                #pragma unroll
                for (int c = 0; c < 4; c++)
                    #pragma unroll
                    for (int d = 0; d < 4; d++)
                        acc[c][d] += src[(c * 4 + d) * 32 + lane];
            }
            #pragma unroll
            for (int d = 0; d < 4; d++) {
                int j = j0 + d;
                float bias = (j < 16) ? __ldg(ug_b + j) : __ldg(cand_b + j - 16);
                #pragma unroll
                for (int c = 0; c < 4; c++)
                    sh_gc[(t0 + c) * 33 + j] = acc[c][d] + bias;
            }
        }
    }
    __syncthreads();

    // ---------------- Phase E: gated update + layernorm ----------------
    {
        const float eta = 1.f / (1.f + __expf(-__ldg(eta_logit)));
        const int s = lane >> 4;
        const int j = lane & 15;
        #pragma unroll
        for (int p = 0; p < 2; p++) {
            int t = (wid << 2) + (p << 1) + s;
            float gp = sh_gc[t * 33 + j];
            float cp = sh_gc[t * 33 + 16 + j];
            float eg = eta * (1.f / (1.f + __expf(-gp)));
            float val = (1.f - eg) * sh_z[t * 17 + j] + eg * tanhf(cp);
            float sum = val;
            #pragma unroll
            for (int msk = 8; msk > 0; msk >>= 1)
                sum += __shfl_xor_sync(0xffffffffu, sum, msk, 16);
            float mu = sum * (1.f / 16.f);
            float dv = val - mu;
            float vs = dv * dv;
            #pragma unroll
            for (int msk = 8; msk > 0; msk >>= 1)
                vs += __shfl_xor_sync(0xffffffffu, vs, msk, 16);
            float var = vs * (1.f / 16.f);
            out_z[(size_t)(b * NN + t) * 16 + j] = dv * rsqrtf(var + 1e-5f);
        }
    }
}

extern "C" void kernel_launch(void* const* d_in, const int* in_sizes, int n_in,
                              void* d_out, int out_size) {
    const float* h        = (const float*)d_in[0];
    const float* u        = (const float*)d_in[1];
    const float* z        = (const float*)d_in[2];
    const float* qd_down  = (const float*)d_in[3];
    const float* qd_up    = (const float*)d_in[4];
    const float* kd_down  = (const float*)d_in[5];
    const float* kd_up    = (const float*)d_in[6];
    const float* vd_down  = (const float*)d_in[7];
    const float* vd_up    = (const float*)d_in[8];
    const float* od_down  = (const float*)d_in[9];
    const float* od_up    = (const float*)d_in[10];
    const float* ug_w     = (const float*)d_in[11];
    const float* ug_b     = (const float*)d_in[12];
    const float* cand_w   = (const float*)d_in[13];
    const float* cand_b   = (const float*)d_in[14];
    const float* eta_logit= (const float*)d_in[15];

    float* o = (float*)d_out;
    float* out_c    = o;                        // 4096*64*128
    float* out_z    = o + (size_t)33554432;     // 4096*64*16
    float* out_attn = o + (size_t)37748736;     // 4096*64*64
    float* out_q    = o + (size_t)54525952;
    float* out_k    = o + (size_t)71303168;
    float* out_v    = o + (size_t)88080384;

    const int smem_bytes = SMEM_FLOATS * sizeof(float);  // 224000
    cudaFuncSetAttribute(memetic_fused_kernel,
                         cudaFuncAttributeMaxDynamicSharedMemorySize, smem_bytes);

    memetic_fused_kernel<<<BB, 512, smem_bytes>>>(
        h, u, z, qd_down, qd_up, kd_down, kd_up, vd_down, vd_up,
        od_down, od_up, ug_w, ug_b, cand_w, cand_b, eta_logit,
        out_c, out_z, out_attn, out_q, out_k, out_v);
}